// round 2
// baseline (speedup 1.0000x reference)
#include <cuda_runtime.h>

#define NB 65536
#define TILE 3
#define NTHREADS 256
#define GRID ((NB + TILE - 1) / TILE)

// global accumulators: ce_sum, mask_sum, sq_sum
__device__ float g_acc[3];

__global__ void init_kernel() {
    g_acc[0] = 0.f; g_acc[1] = 0.f; g_acc[2] = 0.f;
}

__global__ void __launch_bounds__(NTHREADS)
sudoku_main(const float* __restrict__ logits,
            const int* __restrict__ targets,
            const int* __restrict__ puzzles) {
    // 3 batches x 81 cells x 10 floats
    __shared__ float sm[TILE * 81 * 10];          // 2430 floats = 9720 B
    __shared__ float red[3][NTHREADS / 32];

    const int tid = threadIdx.x;

    // ---- stage logits tile into smem, coalesced float2 ----
    {
        const float2* __restrict__ gsrc = (const float2*)logits;
        float2* sdst = (float2*)sm;
        const long long base2 = (long long)blockIdx.x * (TILE * 405);
        const long long tot2 = (long long)NB * 405;   // total float2 count
        #pragma unroll
        for (int i = tid; i < TILE * 405; i += NTHREADS) {
            float2 v = make_float2(0.f, 0.f);
            long long g = base2 + i;
            if (g < tot2) v = gsrc[g];
            sdst[i] = v;
        }
    }
    __syncthreads();

    float ce = 0.f, msk = 0.f, sq = 0.f;

    // ---- phase A: per-cell softmax + CE, write [mask, wp1..wp9] in place ----
    if (tid < TILE * 81) {
        const int b_local = tid / 81;
        const int batch = blockIdx.x * TILE + b_local;
        if (batch < NB) {
            const int cell = tid - b_local * 81;
            const int gi = batch * 81 + cell;
            const int t = targets[gi];
            const int p = puzzles[gi];

            float2* c2 = (float2*)(sm + tid * 10);
            float x[10];
            #pragma unroll
            for (int j = 0; j < 5; j++) {
                float2 v = c2[j];
                x[2 * j] = v.x; x[2 * j + 1] = v.y;
            }
            float m = x[0];
            #pragma unroll
            for (int j = 1; j < 10; j++) m = fmaxf(m, x[j]);
            float e[10], s = 0.f;
            #pragma unroll
            for (int j = 0; j < 10; j++) { e[j] = __expf(x[j] - m); s += e[j]; }
            const float ls = __logf(s);

            msk = (p == 0) ? 1.f : 0.f;

            // predicated select instead of dynamic index (avoid local-mem spill)
            float xt = x[0];
            #pragma unroll
            for (int j = 1; j < 10; j++) xt = (j == t) ? x[j] : xt;
            ce = -(xt - m - ls) * msk;

            const float r = __fdividef(msk, s);   // prob * mask in one scale
            float w[10];
            w[0] = msk;
            #pragma unroll
            for (int j = 1; j < 10; j++) w[j] = e[j] * r;
            #pragma unroll
            for (int j = 0; j < 5; j++) c2[j] = make_float2(w[2 * j], w[2 * j + 1]);
        }
    }
    __syncthreads();

    // ---- phase B: 27 groups x TILE batches, sum 9 cells each ----
    if (tid < TILE * 27) {
        const int b_local = tid / 27;
        const int g = tid - b_local * 27;
        const int bb = b_local * 81;
        float ds[10];
        #pragma unroll
        for (int j = 0; j < 10; j++) ds[j] = 0.f;
        #pragma unroll
        for (int k = 0; k < 9; k++) {
            int cell;
            if (g < 9)       cell = g * 9 + k;                       // row g
            else if (g < 18) cell = k * 9 + (g - 9);                 // col g-9
            else {                                                   // box g-18
                const int bi = g - 18;
                cell = ((bi / 3) * 3 + k / 3) * 9 + (bi % 3) * 3 + (k % 3);
            }
            const float2* c2 = (const float2*)(sm + (bb + cell) * 10);
            #pragma unroll
            for (int j = 0; j < 5; j++) {
                float2 v = c2[j];
                ds[2 * j] += v.x; ds[2 * j + 1] += v.y;
            }
        }
        const float tgt = ds[0] * (1.f / 9.f);   // msum / G
        #pragma unroll
        for (int j = 1; j < 10; j++) {
            const float d = ds[j] - tgt;
            sq += d * d;
        }
    }

    // ---- block reduction ----
    #pragma unroll
    for (int o = 16; o > 0; o >>= 1) {
        ce  += __shfl_down_sync(0xffffffffu, ce,  o);
        msk += __shfl_down_sync(0xffffffffu, msk, o);
        sq  += __shfl_down_sync(0xffffffffu, sq,  o);
    }
    const int w = tid >> 5, lane = tid & 31;
    if (lane == 0) { red[0][w] = ce; red[1][w] = msk; red[2][w] = sq; }
    __syncthreads();
    if (w == 0) {
        const int nw = NTHREADS / 32;
        float a = (lane < nw) ? red[0][lane] : 0.f;
        float b = (lane < nw) ? red[1][lane] : 0.f;
        float c = (lane < nw) ? red[2][lane] : 0.f;
        #pragma unroll
        for (int o = 4; o > 0; o >>= 1) {
            a += __shfl_down_sync(0xffffffffu, a, o);
            b += __shfl_down_sync(0xffffffffu, b, o);
            c += __shfl_down_sync(0xffffffffu, c, o);
        }
        if (lane == 0) {
            atomicAdd(&g_acc[0], a);
            atomicAdd(&g_acc[1], b);
            atomicAdd(&g_acc[2], c);
        }
    }
}

__global__ void final_kernel(float* __restrict__ out) {
    const float ce_sum = g_acc[0];
    const float m_sum  = g_acc[1];
    const float sq_sum = g_acc[2];
    const float ce   = ce_sum / (m_sum + 1e-8f);
    const float cons = sq_sum / ((float)NB * 9.f * 27.f);
    out[0] = ce + 0.1f * cons;
    out[1] = ce;
    out[2] = cons;
}

extern "C" void kernel_launch(void* const* d_in, const int* in_sizes, int n_in,
                              void* d_out, int out_size) {
    const float* logits  = (const float*)d_in[0];
    const int*   targets = (const int*)d_in[1];
    const int*   puzzles = (const int*)d_in[2];
    float* out = (float*)d_out;
    (void)in_sizes; (void)n_in; (void)out_size;

    init_kernel<<<1, 1>>>();
    sudoku_main<<<GRID, NTHREADS>>>(logits, targets, puzzles);
    final_kernel<<<1, 1>>>(out);
}